// round 2
// baseline (speedup 1.0000x reference)
#include <cuda_runtime.h>
#include <cstdint>
#include <cstddef>

// Problem constants (fixed by setup_inputs)
#define NN 4
#define H0 60
#define W0 80
#define H1 60
#define W1 80
#define LL (H0*W0)     // 4800 rows
#define SS (H1*W1)     // 4800 cols
#define THRV 0.2f
#define BR 2

#define TPB 256
#define RPC 8                       // rows per CTA in pass 1
#define NQ (SS/4)                   // 1200 float4 per row
#define KMAX 5                      // ceil(1200/256)

// Scratch (no allocations allowed). Zero-initialized at module load; the
// cleanup kernel restores g_colmax to zero at the end of every launch call.
__device__ unsigned g_colmax[NN*SS];     // colmax as u32 bit pattern (nonneg floats)
__device__ float    g_rowmax[NN*LL];
__device__ int      g_rowj[NN*LL];       // min index achieving rowmax
__device__ int      g_rowcnt[NN*LL];     // count of elements == rowmax

__global__ void cleanup_kernel() {
    int i = blockIdx.x * blockDim.x + threadIdx.x;
    if (i < NN*SS) g_colmax[i] = 0u;
}

__global__ __launch_bounds__(TPB) void pass1(const float4* __restrict__ conf) {
    const int n    = blockIdx.y;
    const int row0 = blockIdx.x * RPC;
    const int t    = threadIdx.x;
    const int warp = t >> 5, lane = t & 31;

    const float4* base = conf + ((size_t)n * LL + row0) * NQ;
    const bool lastok = (t + 4*TPB) < NQ;   // k=4 tail predicate (t < 176)

    float4 cmax[KMAX];
#pragma unroll
    for (int k = 0; k < KMAX; k++) cmax[k] = make_float4(0.f, 0.f, 0.f, 0.f);

    __shared__ float s_max[RPC][8];
    __shared__ int   s_cnt[RPC][8];
    __shared__ int   s_idx[RPC][8];

#pragma unroll
    for (int r = 0; r < RPC; r++) {
        const float4* rowp = base + (size_t)r * NQ;
        float4 v[KMAX];
#pragma unroll
        for (int k = 0; k < 4; k++) v[k] = __ldg(rowp + t + k*TPB);
        v[4] = lastok ? __ldg(rowp + t + 4*TPB) : make_float4(0.f,0.f,0.f,0.f);

        // colmax accumulate + thread-local row max (pure FMAX tree, good ILP)
        float tm = 0.f;
#pragma unroll
        for (int k = 0; k < KMAX; k++) {
            cmax[k].x = fmaxf(cmax[k].x, v[k].x);
            cmax[k].y = fmaxf(cmax[k].y, v[k].y);
            cmax[k].z = fmaxf(cmax[k].z, v[k].z);
            cmax[k].w = fmaxf(cmax[k].w, v[k].w);
            float a = fmaxf(v[k].x, v[k].y);
            float b = fmaxf(v[k].z, v[k].w);
            tm = fmaxf(tm, fmaxf(a, b));
        }

        // warp max via butterfly (all lanes end with wm)
        float wm = tm;
#pragma unroll
        for (int off = 16; off > 0; off >>= 1)
            wm = fmaxf(wm, __shfl_xor_sync(0xffffffffu, wm, off));

        // lazy (cnt, min-idx): only matching lanes rescan their registers
        unsigned lidx = 0x7fffffffu;
        unsigned lcnt = 0u;
        if (tm == wm) {
#pragma unroll
            for (int k = 0; k < KMAX; k++) {
                int j = (t + k*TPB) * 4;
                if (v[k].x == wm) { lcnt++; lidx = min(lidx, (unsigned)j); }
                if (v[k].y == wm) { lcnt++; lidx = min(lidx, (unsigned)(j+1)); }
                if (v[k].z == wm) { lcnt++; lidx = min(lidx, (unsigned)(j+2)); }
                if (v[k].w == wm) { lcnt++; lidx = min(lidx, (unsigned)(j+3)); }
            }
        }
        unsigned wcnt = __reduce_add_sync(0xffffffffu, lcnt);
        unsigned widx = __reduce_min_sync(0xffffffffu, lidx);
        if (lane == 0) {
            s_max[r][warp] = wm;
            s_cnt[r][warp] = (int)wcnt;
            s_idx[r][warp] = (int)widx;
        }
    }
    __syncthreads();

    // combine 8 warp-partials per row
    if (t < RPC) {
        float m = -1.f; int c = 0, ix = 0;
#pragma unroll
        for (int w = 0; w < 8; w++) {
            float om = s_max[t][w];
            if (om > m)       { m = om; c = s_cnt[t][w]; ix = s_idx[t][w]; }
            else if (om == m) { c += s_cnt[t][w]; ix = min(ix, s_idx[t][w]); }
        }
        int gi = n * LL + row0 + t;
        g_rowmax[gi] = m; g_rowj[gi] = ix; g_rowcnt[gi] = c;
    }

    // flush column-max partials
#pragma unroll
    for (int k = 0; k < KMAX; k++) {
        int q = t + k * TPB;
        if (k < 4 || lastok) {
            int j = q * 4;
            unsigned* cm = &g_colmax[n * SS + j];
            atomicMax(cm + 0, __float_as_uint(cmax[k].x));
            atomicMax(cm + 1, __float_as_uint(cmax[k].y));
            atomicMax(cm + 2, __float_as_uint(cmax[k].z));
            atomicMax(cm + 3, __float_as_uint(cmax[k].w));
        }
    }
}

__device__ __forceinline__ bool valid1(int j) {
    int r = j / W1, c = j % W1;
    return (r >= BR) & (r < H1 - BR) & (c >= BR) & (c < W1 - BR);
}

// warp per row: resolve candidate / exact tie rescan, write outputs
__global__ __launch_bounds__(256) void pass2(const float* __restrict__ conf,
                                             float* __restrict__ out) {
    int gw = (blockIdx.x * blockDim.x + threadIdx.x) >> 5;
    int lane = threadIdx.x & 31;
    if (gw >= NN * LL) return;
    int n = gw / LL, i = gw % LL;

    float m   = g_rowmax[gw];
    int   cnt = g_rowcnt[gw];
    int   jc  = g_rowj[gw];

    int r0 = i / W0, c0 = i % W0;
    bool v0 = (r0 >= BR) & (r0 < H0 - BR) & (c0 >= BR) & (c0 < W0 - BR);

    float mconf = 0.f; int jid = 0; float mv = 0.f;
    if (v0 && m > THRV) {
        if (cnt == 1) {
            if (valid1(jc) && g_colmax[n * SS + jc] == __float_as_uint(m)) {
                mv = 1.f; jid = jc; mconf = m;
            }
        } else {
            // exact first-True scan over the (rare) tied row
            const float* rowp = conf + (size_t)n * LL * SS + (size_t)i * SS;
            for (int base = 0; base < SS; base += 32) {
                int j = base + lane;
                bool ok = false;
                float v = rowp[j];
                if (v == m) {
                    ok = valid1(j) && (g_colmax[n * SS + j] == __float_as_uint(v));
                }
                unsigned b = __ballot_sync(0xffffffffu, ok);
                if (b) {
                    jid = base + (__ffs(b) - 1);
                    mv = 1.f; mconf = m;
                    break;
                }
            }
        }
    }
    if (lane == 0) {
        out[gw]              = mconf;       // mconf   [N*L]
        out[NN*LL + gw]      = mv;          // mask_v  [N*L]
        out[2*NN*LL + gw]    = (float)jid;  // j_ids   [N*L]
    }
}

extern "C" void kernel_launch(void* const* d_in, const int* in_sizes, int n_in,
                              void* d_out, int out_size) {
    const float* conf = (const float*)d_in[0];
    float* out = (float*)d_out;

    // Order matters for profiling: pass1 is the first launch of each call so
    // the ncu capture index lands on it. g_colmax is zero at entry (module
    // zero-init on the first call, cleanup_kernel on every later call).
    dim3 g1(LL / RPC, NN);   // 600 x 4 = 2400 CTAs
    pass1<<<g1, TPB>>>((const float4*)conf);
    int warps = NN * LL;     // 19200 warps, warp per row
    pass2<<<(warps * 32 + 255)/256, 256>>>(conf, out);
    cleanup_kernel<<<(NN*SS + 255)/256, 256>>>();
}

// round 3
// speedup vs baseline: 2.6132x; 2.6132x over previous
#include <cuda_runtime.h>
#include <cstdint>
#include <cstddef>

// Problem constants (fixed by setup_inputs)
#define NN 4
#define H0 60
#define W0 80
#define H1 60
#define W1 80
#define LL (H0*W0)     // 4800 rows
#define SS (H1*W1)     // 4800 cols
#define NL (NN*LL)
#define THRV 0.2f
#define BR 2

#define TPB 256
#define RPC 32                      // rows per CTA in pass 1 -> grid 600, one wave
#define NQ (SS/4)                   // 1200 float4 per row
#define TAILN (NQ - 4*TPB)          // 176

// Scratch (no allocations allowed). g_colmax zero at entry: module zero-init on
// first call, cleanup_kernel restores it at the end of every call.
__device__ unsigned g_colmax[NN*SS];     // colmax as u32 bit pattern (nonneg floats)
__device__ float    g_rowmax[NL];
__device__ int      g_rowj[NL];          // min index achieving rowmax
__device__ int      g_rowcnt[NL];        // count of elements == rowmax

__global__ void cleanup_kernel() {
    int i = blockIdx.x * blockDim.x + threadIdx.x;
    if (i < NN*SS) g_colmax[i] = 0u;
}

__global__ __launch_bounds__(TPB, 4) void pass1(const float4* __restrict__ conf) {
    const int n    = blockIdx.y;
    const int row0 = blockIdx.x * RPC;
    const int t    = threadIdx.x;
    const int warp = t >> 5, lane = t & 31;
    const bool tail = t < TAILN;

    const float4* base = conf + ((size_t)n * LL + row0) * NQ + t;

    // colmax accumulators in integer domain (umax == fmax for nonneg floats)
    uint4 c0 = {0,0,0,0}, c1 = {0,0,0,0}, c2 = {0,0,0,0}, c3 = {0,0,0,0}, c4 = {0,0,0,0};

    __shared__ float s_max[RPC][8];
    __shared__ int   s_cnt[RPC][8];
    __shared__ int   s_idx[RPC][8];

#pragma unroll 4
    for (int r = 0; r < RPC; r++) {
        const float4* rp = base + (size_t)r * NQ;
        float4 a0 = __ldg(rp);
        float4 a1 = __ldg(rp + TPB);
        float4 a2 = __ldg(rp + 2*TPB);
        float4 a3 = __ldg(rp + 3*TPB);
        float4 a4 = tail ? __ldg(rp + 4*TPB) : make_float4(0.f,0.f,0.f,0.f);

        // column maxes: integer umax (alu pipe)
        c0.x = umax(c0.x, __float_as_uint(a0.x)); c0.y = umax(c0.y, __float_as_uint(a0.y));
        c0.z = umax(c0.z, __float_as_uint(a0.z)); c0.w = umax(c0.w, __float_as_uint(a0.w));
        c1.x = umax(c1.x, __float_as_uint(a1.x)); c1.y = umax(c1.y, __float_as_uint(a1.y));
        c1.z = umax(c1.z, __float_as_uint(a1.z)); c1.w = umax(c1.w, __float_as_uint(a1.w));
        c2.x = umax(c2.x, __float_as_uint(a2.x)); c2.y = umax(c2.y, __float_as_uint(a2.y));
        c2.z = umax(c2.z, __float_as_uint(a2.z)); c2.w = umax(c2.w, __float_as_uint(a2.w));
        c3.x = umax(c3.x, __float_as_uint(a3.x)); c3.y = umax(c3.y, __float_as_uint(a3.y));
        c3.z = umax(c3.z, __float_as_uint(a3.z)); c3.w = umax(c3.w, __float_as_uint(a3.w));
        c4.x = umax(c4.x, __float_as_uint(a4.x)); c4.y = umax(c4.y, __float_as_uint(a4.y));
        c4.z = umax(c4.z, __float_as_uint(a4.z)); c4.w = umax(c4.w, __float_as_uint(a4.w));

        // row max: packed accumulate (fma pipe), then horizontal
        float4 rm;
        rm.x = fmaxf(fmaxf(a0.x, a1.x), fmaxf(a2.x, a3.x)); rm.x = fmaxf(rm.x, a4.x);
        rm.y = fmaxf(fmaxf(a0.y, a1.y), fmaxf(a2.y, a3.y)); rm.y = fmaxf(rm.y, a4.y);
        rm.z = fmaxf(fmaxf(a0.z, a1.z), fmaxf(a2.z, a3.z)); rm.z = fmaxf(rm.z, a4.z);
        rm.w = fmaxf(fmaxf(a0.w, a1.w), fmaxf(a2.w, a3.w)); rm.w = fmaxf(rm.w, a4.w);
        float tm = fmaxf(fmaxf(rm.x, rm.y), fmaxf(rm.z, rm.w));

        // warp max via single REDUX on bit pattern
        float wm = __uint_as_float(__reduce_max_sync(0xffffffffu, __float_as_uint(tm)));

        // lazy (cnt, min-idx): avg 1 lane/warp enters; registers still live here
        unsigned lcnt = 0u, lidx = 0x7fffffffu;
        if (tm == wm) {
            int j0 = t * 4;
            if (a0.x == wm) { lcnt++; lidx = min(lidx, (unsigned)(j0)); }
            if (a0.y == wm) { lcnt++; lidx = min(lidx, (unsigned)(j0+1)); }
            if (a0.z == wm) { lcnt++; lidx = min(lidx, (unsigned)(j0+2)); }
            if (a0.w == wm) { lcnt++; lidx = min(lidx, (unsigned)(j0+3)); }
            int j1 = (t + TPB) * 4;
            if (a1.x == wm) { lcnt++; lidx = min(lidx, (unsigned)(j1)); }
            if (a1.y == wm) { lcnt++; lidx = min(lidx, (unsigned)(j1+1)); }
            if (a1.z == wm) { lcnt++; lidx = min(lidx, (unsigned)(j1+2)); }
            if (a1.w == wm) { lcnt++; lidx = min(lidx, (unsigned)(j1+3)); }
            int j2 = (t + 2*TPB) * 4;
            if (a2.x == wm) { lcnt++; lidx = min(lidx, (unsigned)(j2)); }
            if (a2.y == wm) { lcnt++; lidx = min(lidx, (unsigned)(j2+1)); }
            if (a2.z == wm) { lcnt++; lidx = min(lidx, (unsigned)(j2+2)); }
            if (a2.w == wm) { lcnt++; lidx = min(lidx, (unsigned)(j2+3)); }
            int j3 = (t + 3*TPB) * 4;
            if (a3.x == wm) { lcnt++; lidx = min(lidx, (unsigned)(j3)); }
            if (a3.y == wm) { lcnt++; lidx = min(lidx, (unsigned)(j3+1)); }
            if (a3.z == wm) { lcnt++; lidx = min(lidx, (unsigned)(j3+2)); }
            if (a3.w == wm) { lcnt++; lidx = min(lidx, (unsigned)(j3+3)); }
            int j4 = (t + 4*TPB) * 4;
            if (a4.x == wm) { lcnt++; lidx = min(lidx, (unsigned)(j4)); }
            if (a4.y == wm) { lcnt++; lidx = min(lidx, (unsigned)(j4+1)); }
            if (a4.z == wm) { lcnt++; lidx = min(lidx, (unsigned)(j4+2)); }
            if (a4.w == wm) { lcnt++; lidx = min(lidx, (unsigned)(j4+3)); }
        }
        unsigned wcnt = __reduce_add_sync(0xffffffffu, lcnt);
        unsigned widx = __reduce_min_sync(0xffffffffu, lidx);
        if (lane == 0) { s_max[r][warp] = wm; s_cnt[r][warp] = (int)wcnt; s_idx[r][warp] = (int)widx; }
    }
    __syncthreads();

    // combine 8 warp-partials per row
    if (t < RPC) {
        float m = -1.f; int c = 0, ix = 0;
#pragma unroll
        for (int w = 0; w < 8; w++) {
            float om = s_max[t][w];
            if (om > m)       { m = om; c = s_cnt[t][w]; ix = s_idx[t][w]; }
            else if (om == m) { c += s_cnt[t][w]; ix = min(ix, s_idx[t][w]); }
        }
        int gi = n * LL + row0 + t;
        g_rowmax[gi] = m; g_rowj[gi] = ix; g_rowcnt[gi] = c;
    }

    // flush column-max partials (fire-and-forget RED.MAX)
    {
        unsigned* cm = &g_colmax[n * SS + 4*t];
        atomicMax(cm+0, c0.x); atomicMax(cm+1, c0.y); atomicMax(cm+2, c0.z); atomicMax(cm+3, c0.w);
        cm += 4*TPB;
        atomicMax(cm+0, c1.x); atomicMax(cm+1, c1.y); atomicMax(cm+2, c1.z); atomicMax(cm+3, c1.w);
        cm += 4*TPB;
        atomicMax(cm+0, c2.x); atomicMax(cm+1, c2.y); atomicMax(cm+2, c2.z); atomicMax(cm+3, c2.w);
        cm += 4*TPB;
        atomicMax(cm+0, c3.x); atomicMax(cm+1, c3.y); atomicMax(cm+2, c3.z); atomicMax(cm+3, c3.w);
        if (tail) {
            cm += 4*TPB;
            atomicMax(cm+0, c4.x); atomicMax(cm+1, c4.y); atomicMax(cm+2, c4.z); atomicMax(cm+3, c4.w);
        }
    }
}

__device__ __forceinline__ bool valid1(int j) {
    int r = j / W1, c = j % W1;
    return (r >= BR) & (r < H1 - BR) & (c >= BR) & (c < W1 - BR);
}

// thread-per-row fast path + CTA-cooperative rescan for the rare ambiguous rows
#define P2B 256
__global__ __launch_bounds__(P2B) void pass2(const float* __restrict__ conf,
                                             float* __restrict__ out) {
    __shared__ int s_list[P2B];
    __shared__ int s_nl;
    __shared__ unsigned s_best;
    const int tid = threadIdx.x;
    const int gw  = blockIdx.x * P2B + tid;        // row id, grid exact: 75*256=19200
    if (tid == 0) s_nl = 0;
    __syncthreads();

    const int n = gw / LL, i = gw % LL;
    const float m  = g_rowmax[gw];
    const int cnt  = g_rowcnt[gw];
    const int jc   = g_rowj[gw];

    const int r0 = i / W0, c0 = i % W0;
    const bool v0 = (r0 >= BR) & (r0 < H0 - BR) & (c0 >= BR) & (c0 < W0 - BR);

    float mconf = 0.f; int jid = 0; float mv = 0.f;
    bool need = false;
    if (v0 && m > THRV) {
        // jc is the global min-index of the row max; if it passes the mask it is
        // the first True regardless of ties.
        if (valid1(jc) && g_colmax[n * SS + jc] == __float_as_uint(m)) {
            mv = 1.f; jid = jc; mconf = m;
        } else if (cnt > 1) {
            need = true;            // a later tied position may pass -> exact rescan
        }
    }
    if (need) { int p = atomicAdd(&s_nl, 1); s_list[p] = tid; }
    __syncthreads();
    if (!need) {
        out[gw]        = mconf;
        out[NL + gw]   = mv;
        out[2*NL + gw] = (float)jid;
    }

    const int nl = s_nl;
    for (int w = 0; w < nl; w++) {
        const int grow = blockIdx.x * P2B + s_list[w];
        const int nn = grow / LL, ii = grow % LL;
        const float mm = g_rowmax[grow];
        const float* rowp = conf + ((size_t)nn * LL + ii) * SS;
        if (tid == 0) s_best = 0x7fffffffu;
        __syncthreads();
        unsigned lb = 0x7fffffffu;
        for (int j = tid; j < SS; j += P2B) {
            float v = rowp[j];
            if (v == mm && valid1(j) && g_colmax[nn * SS + j] == __float_as_uint(v))
                lb = min(lb, (unsigned)j);
        }
        if (lb != 0x7fffffffu) atomicMin(&s_best, lb);
        __syncthreads();
        if (tid == 0) {
            unsigned b = s_best;
            bool hit = (b != 0x7fffffffu);
            out[grow]        = hit ? mm : 0.f;
            out[NL + grow]   = hit ? 1.f : 0.f;
            out[2*NL + grow] = hit ? (float)b : 0.f;
        }
        __syncthreads();
    }
}

extern "C" void kernel_launch(void* const* d_in, const int* in_sizes, int n_in,
                              void* d_out, int out_size) {
    const float* conf = (const float*)d_in[0];
    float* out = (float*)d_out;

    dim3 g1(LL / RPC, NN);            // 150 x 4 = 600 CTAs, one resident wave
    pass1<<<g1, TPB>>>((const float4*)conf);
    pass2<<<NL / P2B, P2B>>>(conf, out);          // 75 CTAs
    cleanup_kernel<<<(NN*SS + 255)/256, 256>>>();
}